// round 7
// baseline (speedup 1.0000x reference)
#include <cuda_runtime.h>

// Net_42176578846907: theta = arctan(xW^T + b) feeds a 10-qubit circuit
//   H^{⊗10} -> RX(theta_q) per qubit -> CNOT ring -> <Z_q>.
// Analytically: H layer -> uniform superposition |+>^{⊗10}; |+> is an RX
// eigenstate (global phase only); the uniform state is invariant under the
// CNOT basis permutation; hence <Z_q> ≡ 0 for every sample and qubit, and
// in the reference's fp32 arithmetic the reduction halves are bit-equal so
// the output is exactly 0.0f. (Verified R1/R2/R4/R5/R6: rel_err = 0.0.)
//
// History (wall / ncu-kernel):
//   R1: 320x256, 1 STG.128/thr          5.92us / 3.81us
//   R2: graph memset node               6.05us / --
//   R4: 80x1024, 1 STG.128/thr          6.05us / 3.78us
//   R5: 148x256 grid-stride unroll      5.12us / 3.94us
//   R6: 160x256, 2 STG.128/thr guarded  5.15us / 3.71us  <- best
// R7: exact-size dispatch to an UNGUARDED variant (no ISETP, no tail
//     branch, ~6 SASS instr/thread); guarded R6 body kept as the general
//     fallback. Expected ~neutral — final floor confirmation.

__global__ __launch_bounds__(256, 1)
void zero_fill_exact(float4* __restrict__ out4) {
    const int base = blockIdx.x * 512 + threadIdx.x;  // always in-bounds
    const float4 z = make_float4(0.0f, 0.0f, 0.0f, 0.0f);
    out4[base]       = z;
    out4[base + 256] = z;
}

__global__ __launch_bounds__(256, 1)
void zero_fill_guarded(float4* __restrict__ out4, int n4,
                       float* __restrict__ out, int n) {
    const int base = blockIdx.x * 512 + threadIdx.x;
    const float4 z = make_float4(0.0f, 0.0f, 0.0f, 0.0f);
    if (base < n4)       out4[base]       = z;
    if (base + 256 < n4) out4[base + 256] = z;
    if (blockIdx.x == 0 && threadIdx.x < 4) {     // scalar tail, general case
        int t = (n4 << 2) + (int)threadIdx.x;
        if (t < n) out[t] = 0.0f;
    }
}

extern "C" void kernel_launch(void* const* d_in, const int* in_sizes, int n_in,
                              void* d_out, int out_size) {
    (void)d_in; (void)in_sizes; (void)n_in;
    int n  = out_size;            // 327680 floats
    int n4 = n >> 2;              // 81920 float4 stores
    if ((n & 3) == 0 && (n4 & 511) == 0 && n4 > 0) {
        // Exact fit: 512 float4 per CTA, no guards needed (hit for this problem)
        zero_fill_exact<<<n4 >> 9, 256>>>((float4*)d_out);
    } else {
        int blocks = (n4 + 511) / 512;
        if (blocks < 1) blocks = 1;
        zero_fill_guarded<<<blocks, 256>>>((float4*)d_out, n4, (float*)d_out, n);
    }
}

// round 8
// speedup vs baseline: 1.0279x; 1.0279x over previous
#include <cuda_runtime.h>

// Net_42176578846907 — FINAL.
// theta = arctan(xW^T + b) feeds a 10-qubit circuit:
//   H^{⊗10} -> RX(theta_q) per qubit -> CNOT ring -> <Z_q>.
// Analytic collapse: the H layer yields the uniform superposition |+>^{⊗10};
// |+> is an RX eigenstate (global phase e^{-it/2} only); the uniform state is
// invariant under the CNOT basis permutations; hence <Z_q> ≡ 0 for every
// sample and qubit. In the reference's fp32 arithmetic every amplitude
// undergoes an identical op sequence, so amplitudes stay BIT-identical and
// each <Z> reduction subtracts two bit-equal sums -> output is exactly 0.0f.
// Verified across 6 benches: rel_err = 0.0.
//
// Optimization history (wall / ncu-kernel-exec):
//   R1: 320x256, 1 STG.128/thr           5.92us / 3.81us
//   R2: graph memset node                6.05us / --
//   R4: 80x1024, 1 STG.128/thr           6.05us / 3.78us
//   R5: 148x256 grid-stride unroll       5.12us / 3.94us
//   R6: 160x256, 2 STG.128/thr, guarded  5.15us / 3.71us
//   R7: 160x256, unguarded exact         5.89us / 3.74us
// Conclusion: kernel exec floor ~3.7us (pure launch/drain; DRAM 0%, issue 3%);
// wall = exec + 1.4-2.3us replay jitter. Node type, grid shape, stores/thread
// and guard elimination all exhausted with <=0.2us effect. This is the floor.

__global__ __launch_bounds__(256, 1)
void zero_fill_exact(float4* __restrict__ out4) {
    const int base = blockIdx.x * 512 + threadIdx.x;  // always in-bounds
    const float4 z = make_float4(0.0f, 0.0f, 0.0f, 0.0f);
    out4[base]       = z;
    out4[base + 256] = z;
}

__global__ __launch_bounds__(256, 1)
void zero_fill_guarded(float4* __restrict__ out4, int n4,
                       float* __restrict__ out, int n) {
    const int base = blockIdx.x * 512 + threadIdx.x;
    const float4 z = make_float4(0.0f, 0.0f, 0.0f, 0.0f);
    if (base < n4)       out4[base]       = z;
    if (base + 256 < n4) out4[base + 256] = z;
    if (blockIdx.x == 0 && threadIdx.x < 4) {     // scalar tail, general case
        int t = (n4 << 2) + (int)threadIdx.x;
        if (t < n) out[t] = 0.0f;
    }
}

extern "C" void kernel_launch(void* const* d_in, const int* in_sizes, int n_in,
                              void* d_out, int out_size) {
    (void)d_in; (void)in_sizes; (void)n_in;
    int n  = out_size;            // 327680 floats for this problem
    int n4 = n >> 2;              // 81920 float4 stores
    if ((n & 3) == 0 && (n4 & 511) == 0 && n4 > 0) {
        // Exact fit (hit here): 512 float4 per CTA, zero guards.
        zero_fill_exact<<<n4 >> 9, 256>>>((float4*)d_out);
    } else {
        int blocks = (n4 + 511) / 512;
        if (blocks < 1) blocks = 1;
        zero_fill_guarded<<<blocks, 256>>>((float4*)d_out, n4, (float*)d_out, n);
    }
}

// round 9
// speedup vs baseline: 1.1646x; 1.1329x over previous
#include <cuda_runtime.h>

// Net_42176578846907 — analytic collapse (FINAL family).
// theta = arctan(xW^T + b) -> H^{⊗10} -> RX layer -> CNOT ring -> <Z_q>.
// H layer gives |+>^{⊗10}; |+> is an RX eigenstate (global phase only);
// the uniform state is invariant under the CNOT permutations; so <Z_q> ≡ 0.
// In the reference's fp32 arithmetic all amplitudes stay bit-identical, so
// each <Z> reduction subtracts bit-equal sums -> output exactly 0.0f.
// Verified rel_err = 0.0 on every passing bench (R1,R2,R4-R8).
//
// History (wall / ncu-kernel-exec):
//   R1 320x256 STG.128x1        5.92 / 3.81      R5 148x256 stride  5.12 / 3.94
//   R2 memset node              6.05 / --        R6 160x256 x2 grd  5.15 / 3.71
//   R4 80x1024 STG.128x1        6.05 / 3.78      R7 exact unguarded 5.89 / 3.74
//   R8 = R7 rerun               5.73 / 3.94  -> both metrics are floor + noise.
// R9: last untried lever — sm_100a 256-bit stores (st.global.v8.f32):
//   80 CTAs x 256 thr x 2 STG.256. Predicted neutral (issue 2.8%, DRAM 0%);
//   completes the lever matrix.

__global__ __launch_bounds__(256, 1)
void zero_fill_exact256(float* __restrict__ out) {
    // Each thread zeroes two 8-float (32B) chunks: CTA covers 4096 floats.
    unsigned base = (blockIdx.x * 4096u) + threadIdx.x * 8u;
    asm volatile(
        "st.global.v8.f32 [%0], {%2,%2,%2,%2,%2,%2,%2,%2};\n\t"
        "st.global.v8.f32 [%1], {%2,%2,%2,%2,%2,%2,%2,%2};\n\t"
        :: "l"(out + base), "l"(out + base + 2048u), "f"(0.0f)
        : "memory");
}

__global__ __launch_bounds__(256, 1)
void zero_fill_guarded(float4* __restrict__ out4, int n4,
                       float* __restrict__ out, int n) {
    const int base = blockIdx.x * 512 + threadIdx.x;
    const float4 z = make_float4(0.0f, 0.0f, 0.0f, 0.0f);
    if (base < n4)       out4[base]       = z;
    if (base + 256 < n4) out4[base + 256] = z;
    if (blockIdx.x == 0 && threadIdx.x < 4) {     // scalar tail, general case
        int t = (n4 << 2) + (int)threadIdx.x;
        if (t < n) out[t] = 0.0f;
    }
}

extern "C" void kernel_launch(void* const* d_in, const int* in_sizes, int n_in,
                              void* d_out, int out_size) {
    (void)d_in; (void)in_sizes; (void)n_in;
    int n  = out_size;            // 327680 floats for this problem
    if (n > 0 && (n % 4096) == 0) {
        // Exact fit (hit here): 80 CTAs, 2 x 256-bit stores per thread.
        zero_fill_exact256<<<n / 4096, 256>>>((float*)d_out);
    } else {
        int n4 = n >> 2;
        int blocks = (n4 + 511) / 512;
        if (blocks < 1) blocks = 1;
        zero_fill_guarded<<<blocks, 256>>>((float4*)d_out, n4, (float*)d_out, n);
    }
}